// round 13
// baseline (speedup 1.0000x reference)
#include <cuda_runtime.h>
#include <math.h>
#include <cstdint>

// Problem constants
#define Bc 2
#define Sc 2048
#define Ec 1024
#define Hc 16
#define GK 1024
#define GN 1024

// ---------------- scratch (device globals; no allocation) ----------------
__device__ float g_X [Bc*Sc*Ec];         // x, tf32-rounded, k-cols 8-group permuted
__device__ float g_Wq[Ec*Ec];            // weights, tf32-rounded, k-cols permuted
__device__ float g_Wk[Ec*Ec];
__device__ float g_Wv[Ec*Ec];
__device__ float g_Wo[Ec*Ec];
__device__ float g_Q [Bc*Sc*Ec];
__device__ float g_K [Bc*Sc*Ec];
__device__ float g_Vt[Bc*Hc*64*Sc];      // V transposed: [bh][d][s'], tf32, kv 8-group permuted
__device__ float g_Qa[Bc*Hc*Sc*128];     // augmented Q (pre-scaled by log2e), tf32, cols permuted
__device__ float g_Ka[Bc*Hc*Sc*128];
__device__ float g_AO[Bc*Sc*Ec];         // flash output, tf32-rounded, cols permuted (O-gemm k)

// ---------------- helpers ----------------
__device__ __forceinline__ uint32_t cvt_tf32(float f) {
    uint32_t r;
    asm("cvt.rna.tf32.f32 %0, %1;" : "=r"(r) : "f"(f));
    return r;
}
__device__ __forceinline__ float cvtf(float f) { return __uint_as_float(cvt_tf32(f)); }
__device__ __forceinline__ void mma8(float c[4], const uint32_t a[4],
                                     uint32_t b0, uint32_t b1) {
    asm volatile(
        "mma.sync.aligned.m16n8k8.row.col.f32.tf32.tf32.f32 "
        "{%0,%1,%2,%3}, {%4,%5,%6,%7}, {%8,%9}, {%0,%1,%2,%3};"
        : "+f"(c[0]), "+f"(c[1]), "+f"(c[2]), "+f"(c[3])
        : "r"(a[0]), "r"(a[1]), "r"(a[2]), "r"(a[3]), "r"(b0), "r"(b1));
}
__device__ __forceinline__ uint32_t smem_u32(const void* p) {
    uint32_t a;
    asm("{ .reg .u64 t; cvta.to.shared.u64 t, %1; cvt.u32.u64 %0, t; }" : "=r"(a) : "l"(p));
    return a;
}
__device__ __forceinline__ void cp16(uint32_t dst, const void* src) {
    asm volatile("cp.async.cg.shared.global [%0], [%1], 16;" :: "r"(dst), "l"(src));
}
#define CP_COMMIT() asm volatile("cp.async.commit_group;" ::: "memory")

// 8-group interleave: position p = 8*(c>>3) + perm8(c&7) holds semantic col c.
// Positions (2t, 2t+1) hold semantic (t, t+4) -> one 64-bit load yields an mma (k, k+4) pair.
__device__ __host__ __forceinline__ int perm8(int r) { return ((r & 3) << 1) | (r >> 2); }

// ================= pre-round to tf32 (RNA) + k-column 8-group permute =================
// Each thread handles one aligned 8-col block: writes pairs (c, c+4) adjacently.
__global__ void preround5(const float4* __restrict__ x,  float4* __restrict__ dx,  int xn8,
                          const float4* __restrict__ w0, float4* __restrict__ dw0,
                          const float4* __restrict__ w1, float4* __restrict__ dw1,
                          const float4* __restrict__ w2, float4* __restrict__ dw2,
                          const float4* __restrict__ w3, float4* __restrict__ dw3, int wn8)
{
    const int y = blockIdx.y;
    const float4* s;
    float4* d;
    int n8;
    if (y == 0)      { s = x;  d = dx;  n8 = xn8; }
    else if (y == 1) { s = w0; d = dw0; n8 = wn8; }
    else if (y == 2) { s = w1; d = dw1; n8 = wn8; }
    else if (y == 3) { s = w2; d = dw2; n8 = wn8; }
    else             { s = w3; d = dw3; n8 = wn8; }
    int i = blockIdx.x * 256 + threadIdx.x;    // 8-col block index
    if (i < n8) {
        float4 a = s[2 * i];
        float4 c = s[2 * i + 1];
        float2* dst = reinterpret_cast<float2*>(d + 2 * i);
        dst[0] = { cvtf(a.x), cvtf(c.x) };
        dst[1] = { cvtf(a.y), cvtf(c.y) };
        dst[2] = { cvtf(a.z), cvtf(c.z) };
        dst[3] = { cvtf(a.w), cvtf(c.w) };
    }
}

// ================= fused QKV tensor-core GEMM (cp.async 3-stage, LDS.64 frags, 2 CTAs/SM) =================
// A and W must be tf32-rounded AND k-col 8-group permuted.
#define GST 36
#define GSTG (2 * 128 * GST)
__global__ void __launch_bounds__(256, 2)
gemm_mma3(const float* __restrict__ A,
          const float* __restrict__ W0, const float* __restrict__ W1, const float* __restrict__ W2,
          const float* __restrict__ b0, const float* __restrict__ b1, const float* __restrict__ b2,
          float* __restrict__ C0, float* __restrict__ C1, float* __restrict__ Vt)
{
    const int z = blockIdx.z;
    const float* W    = (z == 0) ? W0 : ((z == 1) ? W1 : W2);
    const float* bias = (z == 0) ? b0 : ((z == 1) ? b1 : b2);
    float*       C    = (z == 0) ? C0 : ((z == 1) ? C1 : nullptr);

    extern __shared__ uint32_t smg[];
    __shared__ float s_bias[128];

    const int t = threadIdx.x, wid = t >> 5, lane = t & 31;
    const int gr = lane >> 2, tg = lane & 3;
    const int row0 = blockIdx.y * 128, col0 = blockIdx.x * 128;
    const int wm = (wid & 1) * 64, wn = (wid >> 1) * 32;

    if (t < 128) s_bias[t] = bias[col0 + t];

    const uint32_t smgA = smem_u32(smg);

    auto issue = [&](int c) {
        const int st = c % 3;
        const uint32_t baseA = smgA + st * GSTG * 4;
        const uint32_t baseB = baseA + 128 * GST * 4;
        #pragma unroll
        for (int i = 0; i < 4; i++) {
            int pos = t + i * 256;
            int r = pos >> 3, q = pos & 7;
            cp16(baseA + (r * GST + q * 4) * 4, A + (size_t)(row0 + r) * GK + c * 32 + q * 4);
            cp16(baseB + (r * GST + q * 4) * 4, W + (size_t)(col0 + r) * GK + c * 32 + q * 4);
        }
        CP_COMMIT();
    };

    float acc[4][4][4] = {};
    issue(0);
    issue(1);

    const int NC = GK / 32;
    for (int c = 0; c < NC; c++) {
        if (c + 1 < NC) { asm volatile("cp.async.wait_group 1;" ::: "memory"); }
        else            { asm volatile("cp.async.wait_group 0;" ::: "memory"); }
        __syncthreads();
        if (c + 2 < NC) issue(c + 2);

        const uint32_t* Ab = smg + (c % 3) * GSTG;
        const uint32_t* Bb = Ab + 128 * GST;
        #pragma unroll
        for (int kk = 0; kk < 4; kk++) {
            const int kb = kk * 8;
            uint32_t af[4][4];
            #pragma unroll
            for (int mi = 0; mi < 4; mi++) {
                int r = wm + mi * 16 + gr;
                uint2 lo = *reinterpret_cast<const uint2*>(Ab + (r)     * GST + kb + 2 * tg);
                uint2 hi = *reinterpret_cast<const uint2*>(Ab + (r + 8) * GST + kb + 2 * tg);
                af[mi][0] = lo.x;   // A[r][k]
                af[mi][1] = hi.x;   // A[r+8][k]
                af[mi][2] = lo.y;   // A[r][k+4]
                af[mi][3] = hi.y;   // A[r+8][k+4]
            }
            #pragma unroll
            for (int nj = 0; nj < 4; nj++) {
                int n = wn + nj * 8 + gr;
                uint2 bb = *reinterpret_cast<const uint2*>(Bb + n * GST + kb + 2 * tg);
                #pragma unroll
                for (int mi = 0; mi < 4; mi++)
                    mma8(acc[mi][nj], af[mi], bb.x, bb.y);
            }
        }
    }

    if (z < 2) {
        #pragma unroll
        for (int mi = 0; mi < 4; mi++) {
            #pragma unroll
            for (int nj = 0; nj < 4; nj++) {
                int r  = row0 + wm + mi * 16 + gr;
                int cc = col0 + wn + nj * 8 + 2 * tg;
                int bi = wn + nj * 8 + 2 * tg;
                float2 lo = { acc[mi][nj][0] + s_bias[bi], acc[mi][nj][1] + s_bias[bi + 1] };
                float2 hi = { acc[mi][nj][2] + s_bias[bi], acc[mi][nj][3] + s_bias[bi + 1] };
                *reinterpret_cast<float2*>(C + (size_t)r * GN + cc)       = lo;
                *reinterpret_cast<float2*>(C + (size_t)(r + 8) * GN + cc) = hi;
            }
        }
    } else {
        __syncthreads();
        float* Ct = reinterpret_cast<float*>(smg);     // 128 tokens x 133
        #pragma unroll
        for (int mi = 0; mi < 4; mi++) {
            #pragma unroll
            for (int nj = 0; nj < 4; nj++) {
                int r  = wm + mi * 16 + gr;
                int cc = wn + nj * 8 + 2 * tg;
                Ct[(r)     * 133 + cc]     = acc[mi][nj][0] + s_bias[cc];
                Ct[(r)     * 133 + cc + 1] = acc[mi][nj][1] + s_bias[cc + 1];
                Ct[(r + 8) * 133 + cc]     = acc[mi][nj][2] + s_bias[cc];
                Ct[(r + 8) * 133 + cc + 1] = acc[mi][nj][3] + s_bias[cc + 1];
            }
        }
        __syncthreads();
        const int bh_base = (row0 >> 11) * 16 + (col0 >> 6);
        const int sg0 = row0 & (Sc - 1);
        #pragma unroll
        for (int i = 0; i < 64; i++) {
            int idx = t + i * 256;
            int dl = idx >> 7, tok = idx & 127;
            float v = Ct[tok * 133 + dl];
            size_t dst = ((size_t)(bh_base + (dl >> 6)) * 64 + (dl & 63)) * Sc
                       + sg0 + (tok & ~7) + perm8(tok & 7);
            Vt[dst] = cvtf(v);
        }
    }
}

// ================= fused helical: Q and K in ONE launch (z selects) =================
__global__ void __launch_bounds__(256)
hel_fuse2(const float* __restrict__ Q, const float* __restrict__ K,
          const float* __restrict__ Whel, const float* __restrict__ bhel,
          float* __restrict__ Qa, float* __restrict__ Ka)
{
    extern __shared__ float shl[];
    float* Xs   = shl;                    // 128 x 68
    float* Wtmp = Xs + 128 * 68;          // 64 x 68
    float* WsT  = Wtmp + 64 * 68;         // 64 x 64
    float* bs   = WsT + 64 * 64;          // 64

    const float LOG2E = 1.4426950408889634f;
    const int z = blockIdx.z;
    const float* X   = (z == 0) ? Q  : K;
    float*       Aug = (z == 0) ? Qa : Ka;
    const float dscale = (z == 0) ? (0.5f / 8.0f  * LOG2E) : 1.0f;
    const float hscale = (z == 0) ? (0.5f / 32.0f * LOG2E) : 1.0f;

    const int bh = blockIdx.y;
    const int b = bh >> 4, h = bh & 15;
    const int s0 = blockIdx.x * 128;
    const int t = threadIdx.x;

    #pragma unroll
    for (int i = 0; i < 4; i++) {
        int pos = t + i * 256;
        int e = pos >> 4, d4 = pos & 15;
        float4 v = *reinterpret_cast<const float4*>(Whel + (size_t)(h * 64 + e) * 64 + d4 * 4);
        *reinterpret_cast<float4*>(Wtmp + e * 68 + d4 * 4) = v;
    }
    if (t < 64) bs[t] = bhel[h * 64 + t];

    #pragma unroll
    for (int i = 0; i < 4; i++) {
        int pos = t + i * 256;
        int r = pos >> 3, c8 = pos & 7;
        const float* src = X + ((size_t)(b * Sc + s0 + r)) * Ec + h * 64 + c8 * 8;
        float4 a = *reinterpret_cast<const float4*>(src);
        float4 c = *reinterpret_cast<const float4*>(src + 4);
        *reinterpret_cast<float4*>(Xs + r * 68 + c8 * 8)     = a;
        *reinterpret_cast<float4*>(Xs + r * 68 + c8 * 8 + 4) = c;
        float* dst = Aug + ((size_t)bh * Sc + s0 + r) * 128 + c8 * 8;
        float2 p0 = { cvtf(a.x * dscale), cvtf(c.x * dscale) };
        float2 p1 = { cvtf(a.y * dscale), cvtf(c.y * dscale) };
        float2 p2 = { cvtf(a.z * dscale), cvtf(c.z * dscale) };
        float2 p3 = { cvtf(a.w * dscale), cvtf(c.w * dscale) };
        *reinterpret_cast<float2*>(dst)     = p0;
        *reinterpret_cast<float2*>(dst + 2) = p1;
        *reinterpret_cast<float2*>(dst + 4) = p2;
        *reinterpret_cast<float2*>(dst + 6) = p3;
    }
    __syncthreads();

    #pragma unroll
    for (int i = 0; i < 16; i++) {
        int pos = t + i * 256;
        int d = pos >> 6, e = pos & 63;
        WsT[d * 64 + e] = Wtmp[e * 68 + d];
    }
    __syncthreads();

    const int wid = t >> 5, lane = t & 31;
    const int lr = lane >> 3, g = lane & 7;
    const int rbase = wid * 16 + lr * 4;

    float acc[4][8] = {};
    #pragma unroll 4
    for (int d = 0; d < 64; d++) {
        float a[4];
        #pragma unroll
        for (int i = 0; i < 4; i++) a[i] = Xs[(rbase + i) * 68 + d];
        float4 w0 = *reinterpret_cast<const float4*>(WsT + d * 64 + g * 8);
        float4 w1 = *reinterpret_cast<const float4*>(WsT + d * 64 + g * 8 + 4);
        #pragma unroll
        for (int i = 0; i < 4; i++) {
            acc[i][0] += a[i] * w0.x;  acc[i][1] += a[i] * w0.y;
            acc[i][2] += a[i] * w0.z;  acc[i][3] += a[i] * w0.w;
            acc[i][4] += a[i] * w1.x;  acc[i][5] += a[i] * w1.y;
            acc[i][6] += a[i] * w1.z;  acc[i][7] += a[i] * w1.w;
        }
    }

    #pragma unroll
    for (int i = 0; i < 4; i++) {
        int s_src = s0 + rbase + i;
        size_t orow1 = ((size_t)bh * Sc + (s_src >> 1)) * 128;
        size_t orow2 = orow1 + (size_t)(Sc / 2) * 128;
        int par = s_src & 1;
        #pragma unroll
        for (int jj = 0; jj < 4; jj++) {
            float x = acc[i][2 * jj]     + bs[g * 8 + 2 * jj];
            float y = acc[i][2 * jj + 1] + bs[g * 8 + 2 * jj + 1];
            float nrm = sqrtf(x * x + y * y);
            float inv = hscale / fmaxf(nrm, 1e-12f);
            int col = 64 + g * 8 + perm8(2 * jj + par);
            Aug[orow1 + col] = cvtf(x * inv);
            Aug[orow2 + col] = cvtf(y * inv);
        }
    }
}

// ================= flash attention: QT=128/KT=32, 4-stage, exp2, 2 CTAs/SM =================
#define QT 128
#define KT 32
#define KSS 136
#define VSS 40
#define FSTG (KT * KSS + 64 * VSS)

__global__ void __launch_bounds__(256, 2)
flash_mma(const float* __restrict__ Qa, const float* __restrict__ Ka,
          const float* __restrict__ Vt, float* __restrict__ O)
{
    extern __shared__ uint32_t smf[];

    const int bh = blockIdx.y;
    const int b  = bh >> 4, h = bh & 15;
    const int s0 = blockIdx.x * QT;
    const int t  = threadIdx.x, wid = t >> 5, lane = t & 31;
    const int gr = lane >> 2, tg = lane & 3;
    const int prow = wid * 16 + gr;

    const uint32_t smfA = smem_u32(smf);

    const int srcA = (lane & 28) | (tg >> 1);
    const int srcB = srcA + 2;
    const bool oddsel = (tg & 1);
    const int p0 = perm8(2 * tg), p1 = perm8(2 * tg + 1);

    uint32_t qf[16][4];
    {
        const float* Qb = Qa + ((size_t)bh * Sc + s0) * 128;
        #pragma unroll
        for (int kk = 0; kk < 16; kk++) {
            float2 lo = *reinterpret_cast<const float2*>(Qb + (size_t)(prow)     * 128 + kk * 8 + 2 * tg);
            float2 hi = *reinterpret_cast<const float2*>(Qb + (size_t)(prow + 8) * 128 + kk * 8 + 2 * tg);
            qf[kk][0] = __float_as_uint(lo.x);
            qf[kk][1] = __float_as_uint(hi.x);
            qf[kk][2] = __float_as_uint(lo.y);
            qf[kk][3] = __float_as_uint(hi.y);
        }
    }

    auto issue = [&](int it) {
        const int t0 = it * KT;
        const uint32_t baseK = smfA + (it & 3) * FSTG * 4;
        const uint32_t baseV = baseK + KT * KSS * 4;
        const float* Kb = Ka + ((size_t)bh * Sc + t0) * 128;
        #pragma unroll
        for (int i = 0; i < 4; i++) {
            int pos = t + i * 256;
            int r = pos >> 5, c = pos & 31;
            cp16(baseK + (r * KSS + c * 4) * 4, Kb + (size_t)r * 128 + c * 4);
        }
        const float* Vb = Vt + (size_t)bh * 64 * Sc + t0;
        #pragma unroll
        for (int i = 0; i < 2; i++) {
            int pos = t + i * 256;
            int r = pos >> 3, c = pos & 7;
            cp16(baseV + (r * VSS + c * 4) * 4, Vb + (size_t)r * Sc + c * 4);
        }
        CP_COMMIT();
    };

    issue(0);
    issue(1);
    issue(2);

    float l0 = 0.0f, l1 = 0.0f;
    float o[8][4] = {};

    const int NIT = Sc / KT;
    for (int it = 0; it < NIT; it++) {
        const int rem = NIT - 1 - it;
        if (rem >= 2)      { asm volatile("cp.async.wait_group 2;" ::: "memory"); }
        else if (rem == 1) { asm volatile("cp.async.wait_group 1;" ::: "memory"); }
        else               { asm volatile("cp.async.wait_group 0;" ::: "memory"); }
        __syncthreads();
        if (it + 3 < NIT) issue(it + 3);

        const uint32_t* Kp = smf + (it & 3) * FSTG;
        const uint32_t* Vp = Kp + KT * KSS;

        float s[4][4] = {};
        #pragma unroll
        for (int kk = 0; kk < 16; kk++) {
            const int kb = kk * 8;
            #pragma unroll
            for (int nj = 0; nj < 4; nj++) {
                uint2 bb = *reinterpret_cast<const uint2*>(Kp + (nj * 8 + gr) * KSS + kb + 2 * tg);
                mma8(s[nj], qf[kk], bb.x, bb.y);
            }
        }

        #pragma unroll
        for (int nj = 0; nj < 4; nj++) {
            s[nj][0] = exp2f(s[nj][0]);
            s[nj][1] = exp2f(s[nj][1]);
            s[nj][2] = exp2f(s[nj][2]);
            s[nj][3] = exp2f(s[nj][3]);
            l0 += s[nj][0] + s[nj][1];
            l1 += s[nj][2] + s[nj][3];
        }

        #pragma unroll
        for (int kk = 0; kk < 4; kk++) {
            float t00 = __shfl_sync(0xffffffffu, s[kk][0], srcA);
            float t01 = __shfl_sync(0xffffffffu, s[kk][1], srcA);
            float t10 = __shfl_sync(0xffffffffu, s[kk][2], srcA);
            float t11 = __shfl_sync(0xffffffffu, s[kk][3], srcA);
            float t20 = __shfl_sync(0xffffffffu, s[kk][0], srcB);
            float t21 = __shfl_sync(0xffffffffu, s[kk][1], srcB);
            float t30 = __shfl_sync(0xffffffffu, s[kk][2], srcB);
            float t31 = __shfl_sync(0xffffffffu, s[kk][3], srcB);
            uint32_t af[4];
            af[0] = cvt_tf32(oddsel ? t01 : t00);
            af[1] = cvt_tf32(oddsel ? t11 : t10);
            af[2] = cvt_tf32(oddsel ? t21 : t20);
            af[3] = cvt_tf32(oddsel ? t31 : t30);
            const int kb = kk * 8;
            #pragma unroll
            for (int nj = 0; nj < 8; nj++) {
                uint2 bb = *reinterpret_cast<const uint2*>(Vp + (nj * 8 + gr) * VSS + kb + 2 * tg);
                mma8(o[nj], af, bb.x, bb.y);
            }
        }
    }

    l0 += __shfl_xor_sync(0xffffffffu, l0, 1);
    l0 += __shfl_xor_sync(0xffffffffu, l0, 2);
    l1 += __shfl_xor_sync(0xffffffffu, l1, 1);
    l1 += __shfl_xor_sync(0xffffffffu, l1, 2);

    // epilogue: store AO tf32-rounded AND k-col permuted (O-gemm consumes both raw)
    const float invA = 1.0f / l0, invB = 1.0f / l1;
    const int rowA = s0 + prow;
    float* Orow0 = O + (size_t)(b * Sc + rowA) * Ec + h * 64;
    float* Orow1 = O + (size_t)(b * Sc + rowA + 8) * Ec + h * 64;
    #pragma unroll
    for (int nj = 0; nj < 8; nj++) {
        Orow0[nj * 8 + p0] = cvtf(o[nj][0] * invA);
        Orow0[nj * 8 + p1] = cvtf(o[nj][1] * invA);
        Orow1[nj * 8 + p0] = cvtf(o[nj][2] * invB);
        Orow1[nj * 8 + p1] = cvtf(o[nj][3] * invB);
    }
}

// ---------------- host launcher ----------------
extern "C" void kernel_launch(void* const* d_in, const int* in_sizes, int n_in,
                              void* d_out, int out_size)
{
    const float* x    = (const float*)d_in[0];
    const float* Wq   = (const float*)d_in[1];
    const float* bq   = (const float*)d_in[2];
    const float* Wk   = (const float*)d_in[3];
    const float* bk   = (const float*)d_in[4];
    const float* Wv   = (const float*)d_in[5];
    const float* bv   = (const float*)d_in[6];
    const float* Wo   = (const float*)d_in[7];
    const float* bo   = (const float*)d_in[8];
    const float* Whel = (const float*)d_in[9];
    const float* bhel = (const float*)d_in[10];
    float* out = (float*)d_out;

    void *pX, *pWq, *pWk, *pWv, *pWo, *pQ, *pK, *pVt, *pQa, *pKa, *pAO;
    cudaGetSymbolAddress(&pX,  g_X);
    cudaGetSymbolAddress(&pWq, g_Wq);
    cudaGetSymbolAddress(&pWk, g_Wk);
    cudaGetSymbolAddress(&pWv, g_Wv);
    cudaGetSymbolAddress(&pWo, g_Wo);
    cudaGetSymbolAddress(&pQ,  g_Q);
    cudaGetSymbolAddress(&pK,  g_K);
    cudaGetSymbolAddress(&pVt, g_Vt);
    cudaGetSymbolAddress(&pQa, g_Qa);
    cudaGetSymbolAddress(&pKa, g_Ka);
    cudaGetSymbolAddress(&pAO, g_AO);

    const int GEMM_SMEM  = 3 * GSTG * 4;                               // 110592
    const int HEL_SMEM   = (128 * 68 + 64 * 68 + 64 * 64 + 64) * 4;    // 68864
    const int FLASH_SMEM = 4 * FSTG * 4;                               // 110592
    cudaFuncSetAttribute(gemm_mma3, cudaFuncAttributeMaxDynamicSharedMemorySize, GEMM_SMEM);
    cudaFuncSetAttribute(hel_fuse2, cudaFuncAttributeMaxDynamicSharedMemorySize, HEL_SMEM);
    cudaFuncSetAttribute(flash_mma, cudaFuncAttributeMaxDynamicSharedMemorySize, FLASH_SMEM);

    dim3 blk(256);

    // 0) pre-round + k-permute x and the 4 weights in one launch
    const int xN8 = Bc * Sc * Ec / 8;     // 524288
    const int wN8 = Ec * Ec / 8;          // 131072
    dim3 prGrid((xN8 + 255) / 256, 5);
    preround5<<<prGrid, blk>>>((const float4*)x,  (float4*)pX,  xN8,
                               (const float4*)Wq, (float4*)pWq,
                               (const float4*)Wk, (float4*)pWk,
                               (const float4*)Wv, (float4*)pWv,
                               (const float4*)Wo, (float4*)pWo, wN8);

    // 1) Q, K, V projections (3-stage cp.async GEMM, LDS.64 fragments)
    dim3 qkvGrid(GN / 128, (Bc * Sc) / 128, 3);
    gemm_mma3<<<qkvGrid, blk, GEMM_SMEM>>>((const float*)pX,
                                           (const float*)pWq, (const float*)pWk, (const float*)pWv,
                                           bq, bk, bv,
                                           (float*)pQ, (float*)pK, (float*)pVt);

    // 2) fused helical: Q and K in one launch (Q scales include log2e)
    dim3 helGrid(Sc / 128, Bc * Hc, 2);
    hel_fuse2<<<helGrid, blk, HEL_SMEM>>>((const float*)pQ, (const float*)pK,
                                          Whel, bhel, (float*)pQa, (float*)pKa);

    // 3) flash attention (4-stage, exp2, permuted AO epilogue)
    dim3 faGrid(Sc / QT, Bc * Hc);
    flash_mma<<<faGrid, blk, FLASH_SMEM>>>((const float*)pQa, (const float*)pKa,
                                           (const float*)pVt, (float*)pAO);

    // 4) output projection (AO and Wo both k-permuted consistently)
    dim3 oGrid(GN / 128, (Bc * Sc) / 128, 1);
    gemm_mma3<<<oGrid, blk, GEMM_SMEM>>>((const float*)pAO,
                                         (const float*)pWo, (const float*)pWo, (const float*)pWo,
                                         bo, bo, bo,
                                         out, out, nullptr);
}

// round 14
// speedup vs baseline: 1.0973x; 1.0973x over previous
#include <cuda_runtime.h>
#include <math.h>
#include <cstdint>

// Problem constants
#define Bc 2
#define Sc 2048
#define Ec 1024
#define Hc 16
#define GK 1024
#define GN 1024

// ---------------- scratch (device globals; no allocation) ----------------
__device__ float g_X [Bc*Sc*Ec];         // x, tf32-rounded
__device__ float g_Wq[Ec*Ec];            // weights, tf32-rounded
__device__ float g_Wk[Ec*Ec];
__device__ float g_Wv[Ec*Ec];
__device__ float g_Wo[Ec*Ec];
__device__ float g_Q [Bc*Sc*Ec];
__device__ float g_K [Bc*Sc*Ec];
__device__ float g_Vt[Bc*Hc*64*Sc];      // V transposed: [bh][d][s'], tf32, kv 8-group permuted
__device__ float g_Qa[Bc*Hc*Sc*128];     // augmented Q (pre-scaled by log2e), tf32, cols permuted
__device__ float g_Ka[Bc*Hc*Sc*128];
__device__ float g_AO[Bc*Sc*Ec];         // flash output, tf32-rounded

// ---------------- helpers ----------------
__device__ __forceinline__ uint32_t cvt_tf32(float f) {
    uint32_t r;
    asm("cvt.rna.tf32.f32 %0, %1;" : "=r"(r) : "f"(f));
    return r;
}
__device__ __forceinline__ float cvtf(float f) { return __uint_as_float(cvt_tf32(f)); }
__device__ __forceinline__ void mma8(float c[4], const uint32_t a[4],
                                     uint32_t b0, uint32_t b1) {
    asm volatile(
        "mma.sync.aligned.m16n8k8.row.col.f32.tf32.tf32.f32 "
        "{%0,%1,%2,%3}, {%4,%5,%6,%7}, {%8,%9}, {%0,%1,%2,%3};"
        : "+f"(c[0]), "+f"(c[1]), "+f"(c[2]), "+f"(c[3])
        : "r"(a[0]), "r"(a[1]), "r"(a[2]), "r"(a[3]), "r"(b0), "r"(b1));
}
__device__ __forceinline__ uint32_t smem_u32(const void* p) {
    uint32_t a;
    asm("{ .reg .u64 t; cvta.to.shared.u64 t, %1; cvt.u32.u64 %0, t; }" : "=r"(a) : "l"(p));
    return a;
}
__device__ __forceinline__ void cp16(uint32_t dst, const void* src) {
    asm volatile("cp.async.cg.shared.global [%0], [%1], 16;" :: "r"(dst), "l"(src));
}
#define CP_COMMIT() asm volatile("cp.async.commit_group;" ::: "memory")

// 8-group interleave: position p = 8*(c>>3) + perm8(c&7) holds semantic col c.
__device__ __host__ __forceinline__ int perm8(int r) { return ((r & 3) << 1) | (r >> 2); }

// ================= pre-round to tf32 (RNA), packed 1D grid (no idle blocks) =================
// Block ranges: [0, XB) -> x ; then 4 weight segments of WB blocks each.
__global__ void preround5(const float4* __restrict__ x,  float4* __restrict__ dx,  int xn4,
                          const float4* __restrict__ w0, float4* __restrict__ dw0,
                          const float4* __restrict__ w1, float4* __restrict__ dw1,
                          const float4* __restrict__ w2, float4* __restrict__ dw2,
                          const float4* __restrict__ w3, float4* __restrict__ dw3, int wn4,
                          int XB, int WB)
{
    int blk = blockIdx.x;
    const float4* s;
    float4* d;
    int n4, base;
    if (blk < XB)               { s = x;  d = dx;  n4 = xn4; base = blk; }
    else if (blk < XB + WB)     { s = w0; d = dw0; n4 = wn4; base = blk - XB; }
    else if (blk < XB + 2 * WB) { s = w1; d = dw1; n4 = wn4; base = blk - XB - WB; }
    else if (blk < XB + 3 * WB) { s = w2; d = dw2; n4 = wn4; base = blk - XB - 2 * WB; }
    else                        { s = w3; d = dw3; n4 = wn4; base = blk - XB - 3 * WB; }
    int i = base * 256 + threadIdx.x;
    if (i < n4) {
        float4 v = s[i];
        v.x = cvtf(v.x); v.y = cvtf(v.y); v.z = cvtf(v.z); v.w = cvtf(v.w);
        d[i] = v;
    }
}

// ================= fused QKV tensor-core GEMM (cp.async 3-stage, 2 CTAs/SM) =================
#define GST 36
#define GSTG (2 * 128 * GST)
__global__ void __launch_bounds__(256, 2)
gemm_mma3(const float* __restrict__ A,
          const float* __restrict__ W0, const float* __restrict__ W1, const float* __restrict__ W2,
          const float* __restrict__ b0, const float* __restrict__ b1, const float* __restrict__ b2,
          float* __restrict__ C0, float* __restrict__ C1, float* __restrict__ Vt)
{
    const int z = blockIdx.z;
    const float* W    = (z == 0) ? W0 : ((z == 1) ? W1 : W2);
    const float* bias = (z == 0) ? b0 : ((z == 1) ? b1 : b2);
    float*       C    = (z == 0) ? C0 : ((z == 1) ? C1 : nullptr);

    extern __shared__ uint32_t smg[];
    __shared__ float s_bias[128];

    const int t = threadIdx.x, wid = t >> 5, lane = t & 31;
    const int gr = lane >> 2, tg = lane & 3;
    const int row0 = blockIdx.y * 128, col0 = blockIdx.x * 128;
    const int wm = (wid & 1) * 64, wn = (wid >> 1) * 32;

    if (t < 128) s_bias[t] = bias[col0 + t];

    const uint32_t smgA = smem_u32(smg);

    auto issue = [&](int c) {
        const int st = c % 3;
        const uint32_t baseA = smgA + st * GSTG * 4;
        const uint32_t baseB = baseA + 128 * GST * 4;
        #pragma unroll
        for (int i = 0; i < 4; i++) {
            int pos = t + i * 256;
            int r = pos >> 3, q = pos & 7;
            cp16(baseA + (r * GST + q * 4) * 4, A + (size_t)(row0 + r) * GK + c * 32 + q * 4);
            cp16(baseB + (r * GST + q * 4) * 4, W + (size_t)(col0 + r) * GK + c * 32 + q * 4);
        }
        CP_COMMIT();
    };

    float acc[4][4][4] = {};
    issue(0);
    issue(1);

    const int NC = GK / 32;
    for (int c = 0; c < NC; c++) {
        if (c + 1 < NC) { asm volatile("cp.async.wait_group 1;" ::: "memory"); }
        else            { asm volatile("cp.async.wait_group 0;" ::: "memory"); }
        __syncthreads();
        if (c + 2 < NC) issue(c + 2);

        const uint32_t* Ab = smg + (c % 3) * GSTG;
        const uint32_t* Bb = Ab + 128 * GST;
        #pragma unroll
        for (int kk = 0; kk < 4; kk++) {
            const int kb = kk * 8;
            uint32_t af[4][4];
            #pragma unroll
            for (int mi = 0; mi < 4; mi++) {
                int r = wm + mi * 16 + gr;
                af[mi][0] = Ab[(r)     * GST + kb + tg];
                af[mi][1] = Ab[(r + 8) * GST + kb + tg];
                af[mi][2] = Ab[(r)     * GST + kb + tg + 4];
                af[mi][3] = Ab[(r + 8) * GST + kb + tg + 4];
            }
            #pragma unroll
            for (int nj = 0; nj < 4; nj++) {
                int n = wn + nj * 8 + gr;
                uint32_t bb0 = Bb[n * GST + kb + tg];
                uint32_t bb1 = Bb[n * GST + kb + tg + 4];
                #pragma unroll
                for (int mi = 0; mi < 4; mi++)
                    mma8(acc[mi][nj], af[mi], bb0, bb1);
            }
        }
    }

    if (z < 2) {
        #pragma unroll
        for (int mi = 0; mi < 4; mi++) {
            #pragma unroll
            for (int nj = 0; nj < 4; nj++) {
                int r  = row0 + wm + mi * 16 + gr;
                int cc = col0 + wn + nj * 8 + 2 * tg;
                int bi = wn + nj * 8 + 2 * tg;
                float2 lo = { acc[mi][nj][0] + s_bias[bi], acc[mi][nj][1] + s_bias[bi + 1] };
                float2 hi = { acc[mi][nj][2] + s_bias[bi], acc[mi][nj][3] + s_bias[bi + 1] };
                *reinterpret_cast<float2*>(C + (size_t)r * GN + cc)       = lo;
                *reinterpret_cast<float2*>(C + (size_t)(r + 8) * GN + cc) = hi;
            }
        }
    } else {
        __syncthreads();
        float* Ct = reinterpret_cast<float*>(smg);     // 128 tokens x 133
        #pragma unroll
        for (int mi = 0; mi < 4; mi++) {
            #pragma unroll
            for (int nj = 0; nj < 4; nj++) {
                int r  = wm + mi * 16 + gr;
                int cc = wn + nj * 8 + 2 * tg;
                Ct[(r)     * 133 + cc]     = acc[mi][nj][0] + s_bias[cc];
                Ct[(r)     * 133 + cc + 1] = acc[mi][nj][1] + s_bias[cc + 1];
                Ct[(r + 8) * 133 + cc]     = acc[mi][nj][2] + s_bias[cc];
                Ct[(r + 8) * 133 + cc + 1] = acc[mi][nj][3] + s_bias[cc + 1];
            }
        }
        __syncthreads();
        const int bh_base = (row0 >> 11) * 16 + (col0 >> 6);
        const int sg0 = row0 & (Sc - 1);
        #pragma unroll
        for (int i = 0; i < 64; i++) {
            int idx = t + i * 256;
            int dl = idx >> 7, tok = idx & 127;
            float v = Ct[tok * 133 + dl];
            size_t dst = ((size_t)(bh_base + (dl >> 6)) * 64 + (dl & 63)) * Sc
                       + sg0 + (tok & ~7) + perm8(tok & 7);
            Vt[dst] = cvtf(v);
        }
    }
}

// ================= fused helical: Q and K in ONE launch (z selects) =================
__global__ void __launch_bounds__(256)
hel_fuse2(const float* __restrict__ Q, const float* __restrict__ K,
          const float* __restrict__ Whel, const float* __restrict__ bhel,
          float* __restrict__ Qa, float* __restrict__ Ka)
{
    extern __shared__ float shl[];
    float* Xs   = shl;                    // 128 x 68
    float* Wtmp = Xs + 128 * 68;          // 64 x 68
    float* WsT  = Wtmp + 64 * 68;         // 64 x 64
    float* bs   = WsT + 64 * 64;          // 64

    const float LOG2E = 1.4426950408889634f;
    const int z = blockIdx.z;
    const float* X   = (z == 0) ? Q  : K;
    float*       Aug = (z == 0) ? Qa : Ka;
    const float dscale = (z == 0) ? (0.5f / 8.0f  * LOG2E) : 1.0f;
    const float hscale = (z == 0) ? (0.5f / 32.0f * LOG2E) : 1.0f;

    const int bh = blockIdx.y;
    const int b = bh >> 4, h = bh & 15;
    const int s0 = blockIdx.x * 128;
    const int t = threadIdx.x;

    #pragma unroll
    for (int i = 0; i < 4; i++) {
        int pos = t + i * 256;
        int e = pos >> 4, d4 = pos & 15;
        float4 v = *reinterpret_cast<const float4*>(Whel + (size_t)(h * 64 + e) * 64 + d4 * 4);
        *reinterpret_cast<float4*>(Wtmp + e * 68 + d4 * 4) = v;
    }
    if (t < 64) bs[t] = bhel[h * 64 + t];

    #pragma unroll
    for (int i = 0; i < 4; i++) {
        int pos = t + i * 256;
        int r = pos >> 3, c8 = pos & 7;
        const float* src = X + ((size_t)(b * Sc + s0 + r)) * Ec + h * 64 + c8 * 8;
        float4 a = *reinterpret_cast<const float4*>(src);
        float4 c = *reinterpret_cast<const float4*>(src + 4);
        *reinterpret_cast<float4*>(Xs + r * 68 + c8 * 8)     = a;
        *reinterpret_cast<float4*>(Xs + r * 68 + c8 * 8 + 4) = c;
        float* dst = Aug + ((size_t)bh * Sc + s0 + r) * 128 + c8 * 8;
        float2 p0 = { cvtf(a.x * dscale), cvtf(c.x * dscale) };
        float2 p1 = { cvtf(a.y * dscale), cvtf(c.y * dscale) };
        float2 p2 = { cvtf(a.z * dscale), cvtf(c.z * dscale) };
        float2 p3 = { cvtf(a.w * dscale), cvtf(c.w * dscale) };
        *reinterpret_cast<float2*>(dst)     = p0;
        *reinterpret_cast<float2*>(dst + 2) = p1;
        *reinterpret_cast<float2*>(dst + 4) = p2;
        *reinterpret_cast<float2*>(dst + 6) = p3;
    }
    __syncthreads();

    #pragma unroll
    for (int i = 0; i < 16; i++) {
        int pos = t + i * 256;
        int d = pos >> 6, e = pos & 63;
        WsT[d * 64 + e] = Wtmp[e * 68 + d];
    }
    __syncthreads();

    const int wid = t >> 5, lane = t & 31;
    const int lr = lane >> 3, g = lane & 7;
    const int rbase = wid * 16 + lr * 4;

    float acc[4][8] = {};
    #pragma unroll 4
    for (int d = 0; d < 64; d++) {
        float a[4];
        #pragma unroll
        for (int i = 0; i < 4; i++) a[i] = Xs[(rbase + i) * 68 + d];
        float4 w0 = *reinterpret_cast<const float4*>(WsT + d * 64 + g * 8);
        float4 w1 = *reinterpret_cast<const float4*>(WsT + d * 64 + g * 8 + 4);
        #pragma unroll
        for (int i = 0; i < 4; i++) {
            acc[i][0] += a[i] * w0.x;  acc[i][1] += a[i] * w0.y;
            acc[i][2] += a[i] * w0.z;  acc[i][3] += a[i] * w0.w;
            acc[i][4] += a[i] * w1.x;  acc[i][5] += a[i] * w1.y;
            acc[i][6] += a[i] * w1.z;  acc[i][7] += a[i] * w1.w;
        }
    }

    #pragma unroll
    for (int i = 0; i < 4; i++) {
        int s_src = s0 + rbase + i;
        size_t orow1 = ((size_t)bh * Sc + (s_src >> 1)) * 128;
        size_t orow2 = orow1 + (size_t)(Sc / 2) * 128;
        int par = s_src & 1;
        #pragma unroll
        for (int jj = 0; jj < 4; jj++) {
            float x = acc[i][2 * jj]     + bs[g * 8 + 2 * jj];
            float y = acc[i][2 * jj + 1] + bs[g * 8 + 2 * jj + 1];
            float nrm = sqrtf(x * x + y * y);
            float inv = hscale / fmaxf(nrm, 1e-12f);
            int col = 64 + g * 8 + perm8(2 * jj + par);
            Aug[orow1 + col] = cvtf(x * inv);
            Aug[orow2 + col] = cvtf(y * inv);
        }
    }
}

// ================= flash attention: QT=128/KT=32, 4-stage, exp2, 2 CTAs/SM =================
#define QT 128
#define KT 32
#define KSS 136
#define VSS 40
#define FSTG (KT * KSS + 64 * VSS)

__global__ void __launch_bounds__(256, 2)
flash_mma(const float* __restrict__ Qa, const float* __restrict__ Ka,
          const float* __restrict__ Vt, float* __restrict__ O)
{
    extern __shared__ uint32_t smf[];

    const int bh = blockIdx.y;
    const int b  = bh >> 4, h = bh & 15;
    const int s0 = blockIdx.x * QT;
    const int t  = threadIdx.x, wid = t >> 5, lane = t & 31;
    const int gr = lane >> 2, tg = lane & 3;
    const int prow = wid * 16 + gr;

    const uint32_t smfA = smem_u32(smf);

    const int srcA = (lane & 28) | (tg >> 1);
    const int srcB = srcA + 2;
    const bool oddsel = (tg & 1);

    uint32_t qf[16][4];
    {
        const float* Qb = Qa + ((size_t)bh * Sc + s0) * 128;
        #pragma unroll
        for (int kk = 0; kk < 16; kk++) {
            float2 lo = *reinterpret_cast<const float2*>(Qb + (size_t)(prow)     * 128 + kk * 8 + 2 * tg);
            float2 hi = *reinterpret_cast<const float2*>(Qb + (size_t)(prow + 8) * 128 + kk * 8 + 2 * tg);
            qf[kk][0] = __float_as_uint(lo.x);
            qf[kk][1] = __float_as_uint(hi.x);
            qf[kk][2] = __float_as_uint(lo.y);
            qf[kk][3] = __float_as_uint(hi.y);
        }
    }

    auto issue = [&](int it) {
        const int t0 = it * KT;
        const uint32_t baseK = smfA + (it & 3) * FSTG * 4;
        const uint32_t baseV = baseK + KT * KSS * 4;
        const float* Kb = Ka + ((size_t)bh * Sc + t0) * 128;
        #pragma unroll
        for (int i = 0; i < 4; i++) {
            int pos = t + i * 256;
            int r = pos >> 5, c = pos & 31;
            cp16(baseK + (r * KSS + c * 4) * 4, Kb + (size_t)r * 128 + c * 4);
        }
        const float* Vb = Vt + (size_t)bh * 64 * Sc + t0;
        #pragma unroll
        for (int i = 0; i < 2; i++) {
            int pos = t + i * 256;
            int r = pos >> 3, c = pos & 7;
            cp16(baseV + (r * VSS + c * 4) * 4, Vb + (size_t)r * Sc + c * 4);
        }
        CP_COMMIT();
    };

    issue(0);
    issue(1);
    issue(2);

    float l0 = 0.0f, l1 = 0.0f;
    float o[8][4] = {};

    const int NIT = Sc / KT;
    for (int it = 0; it < NIT; it++) {
        const int rem = NIT - 1 - it;
        if (rem >= 2)      { asm volatile("cp.async.wait_group 2;" ::: "memory"); }
        else if (rem == 1) { asm volatile("cp.async.wait_group 1;" ::: "memory"); }
        else               { asm volatile("cp.async.wait_group 0;" ::: "memory"); }
        __syncthreads();
        if (it + 3 < NIT) issue(it + 3);

        const uint32_t* Kp = smf + (it & 3) * FSTG;
        const uint32_t* Vp = Kp + KT * KSS;

        float s[4][4] = {};
        #pragma unroll
        for (int kk = 0; kk < 16; kk++) {
            const int kb = kk * 8;
            #pragma unroll
            for (int nj = 0; nj < 4; nj++) {
                uint2 bb = *reinterpret_cast<const uint2*>(Kp + (nj * 8 + gr) * KSS + kb + 2 * tg);
                mma8(s[nj], qf[kk], bb.x, bb.y);
            }
        }

        #pragma unroll
        for (int nj = 0; nj < 4; nj++) {
            s[nj][0] = exp2f(s[nj][0]);
            s[nj][1] = exp2f(s[nj][1]);
            s[nj][2] = exp2f(s[nj][2]);
            s[nj][3] = exp2f(s[nj][3]);
            l0 += s[nj][0] + s[nj][1];
            l1 += s[nj][2] + s[nj][3];
        }

        #pragma unroll
        for (int kk = 0; kk < 4; kk++) {
            float t00 = __shfl_sync(0xffffffffu, s[kk][0], srcA);
            float t01 = __shfl_sync(0xffffffffu, s[kk][1], srcA);
            float t10 = __shfl_sync(0xffffffffu, s[kk][2], srcA);
            float t11 = __shfl_sync(0xffffffffu, s[kk][3], srcA);
            float t20 = __shfl_sync(0xffffffffu, s[kk][0], srcB);
            float t21 = __shfl_sync(0xffffffffu, s[kk][1], srcB);
            float t30 = __shfl_sync(0xffffffffu, s[kk][2], srcB);
            float t31 = __shfl_sync(0xffffffffu, s[kk][3], srcB);
            uint32_t af[4];
            af[0] = cvt_tf32(oddsel ? t01 : t00);
            af[1] = cvt_tf32(oddsel ? t11 : t10);
            af[2] = cvt_tf32(oddsel ? t21 : t20);
            af[3] = cvt_tf32(oddsel ? t31 : t30);
            const int kb = kk * 8;
            #pragma unroll
            for (int nj = 0; nj < 8; nj++) {
                uint2 bb = *reinterpret_cast<const uint2*>(Vp + (nj * 8 + gr) * VSS + kb + 2 * tg);
                mma8(o[nj], af, bb.x, bb.y);
            }
        }
    }

    l0 += __shfl_xor_sync(0xffffffffu, l0, 1);
    l0 += __shfl_xor_sync(0xffffffffu, l0, 2);
    l1 += __shfl_xor_sync(0xffffffffu, l1, 1);
    l1 += __shfl_xor_sync(0xffffffffu, l1, 2);

    const float invA = 1.0f / l0, invB = 1.0f / l1;
    const int rowA = s0 + prow;
    #pragma unroll
    for (int nj = 0; nj < 8; nj++) {
        int col = h * 64 + nj * 8 + 2 * tg;
        float2 lo = { cvtf(o[nj][0] * invA), cvtf(o[nj][1] * invA) };
        float2 hi = { cvtf(o[nj][2] * invB), cvtf(o[nj][3] * invB) };
        *reinterpret_cast<float2*>(O + (size_t)(b * Sc + rowA) * Ec + col)     = lo;
        *reinterpret_cast<float2*>(O + (size_t)(b * Sc + rowA + 8) * Ec + col) = hi;
    }
}

// ---------------- host launcher ----------------
extern "C" void kernel_launch(void* const* d_in, const int* in_sizes, int n_in,
                              void* d_out, int out_size)
{
    const float* x    = (const float*)d_in[0];
    const float* Wq   = (const float*)d_in[1];
    const float* bq   = (const float*)d_in[2];
    const float* Wk   = (const float*)d_in[3];
    const float* bk   = (const float*)d_in[4];
    const float* Wv   = (const float*)d_in[5];
    const float* bv   = (const float*)d_in[6];
    const float* Wo   = (const float*)d_in[7];
    const float* bo   = (const float*)d_in[8];
    const float* Whel = (const float*)d_in[9];
    const float* bhel = (const float*)d_in[10];
    float* out = (float*)d_out;

    void *pX, *pWq, *pWk, *pWv, *pWo, *pQ, *pK, *pVt, *pQa, *pKa, *pAO;
    cudaGetSymbolAddress(&pX,  g_X);
    cudaGetSymbolAddress(&pWq, g_Wq);
    cudaGetSymbolAddress(&pWk, g_Wk);
    cudaGetSymbolAddress(&pWv, g_Wv);
    cudaGetSymbolAddress(&pWo, g_Wo);
    cudaGetSymbolAddress(&pQ,  g_Q);
    cudaGetSymbolAddress(&pK,  g_K);
    cudaGetSymbolAddress(&pVt, g_Vt);
    cudaGetSymbolAddress(&pQa, g_Qa);
    cudaGetSymbolAddress(&pKa, g_Ka);
    cudaGetSymbolAddress(&pAO, g_AO);

    const int GEMM_SMEM  = 3 * GSTG * 4;                               // 110592
    const int HEL_SMEM   = (128 * 68 + 64 * 68 + 64 * 64 + 64) * 4;    // 68864
    const int FLASH_SMEM = 4 * FSTG * 4;                               // 110592
    cudaFuncSetAttribute(gemm_mma3, cudaFuncAttributeMaxDynamicSharedMemorySize, GEMM_SMEM);
    cudaFuncSetAttribute(hel_fuse2, cudaFuncAttributeMaxDynamicSharedMemorySize, HEL_SMEM);
    cudaFuncSetAttribute(flash_mma, cudaFuncAttributeMaxDynamicSharedMemorySize, FLASH_SMEM);

    dim3 blk(256);

    // 0) pre-round x and the 4 weights, packed 1D grid (no idle blocks)
    const int xN4 = Bc * Sc * Ec / 4;     // 1048576
    const int wN4 = Ec * Ec / 4;          // 262144
    const int XB = (xN4 + 255) / 256;     // 4096
    const int WB = (wN4 + 255) / 256;     // 1024
    preround5<<<XB + 4 * WB, blk>>>((const float4*)x,  (float4*)pX,  xN4,
                                    (const float4*)Wq, (float4*)pWq,
                                    (const float4*)Wk, (float4*)pWk,
                                    (const float4*)Wv, (float4*)pWv,
                                    (const float4*)Wo, (float4*)pWo, wN4,
                                    XB, WB);

    // 1) Q, K, V projections (3-stage cp.async GEMM)
    dim3 qkvGrid(GN / 128, (Bc * Sc) / 128, 3);
    gemm_mma3<<<qkvGrid, blk, GEMM_SMEM>>>((const float*)pX,
                                           (const float*)pWq, (const float*)pWk, (const float*)pWv,
                                           bq, bk, bv,
                                           (float*)pQ, (float*)pK, (float*)pVt);

    // 2) fused helical: Q and K in one launch (Q scales include log2e)
    dim3 helGrid(Sc / 128, Bc * Hc, 2);
    hel_fuse2<<<helGrid, blk, HEL_SMEM>>>((const float*)pQ, (const float*)pK,
                                          Whel, bhel, (float*)pQa, (float*)pKa);

    // 3) flash attention (4-stage, exp2)
    dim3 faGrid(Sc / QT, Bc * Hc);
    flash_mma<<<faGrid, blk, FLASH_SMEM>>>((const float*)pQa, (const float*)pKa,
                                           (const float*)pVt, (float*)pAO);

    // 4) output projection
    dim3 oGrid(GN / 128, (Bc * Sc) / 128, 1);
    gemm_mma3<<<oGrid, blk, GEMM_SMEM>>>((const float*)pAO,
                                         (const float*)pWo, (const float*)pWo, (const float*)pWo,
                                         bo, bo, bo,
                                         out, out, nullptr);
}

// round 16
// speedup vs baseline: 1.1054x; 1.0074x over previous
#include <cuda_runtime.h>
#include <math.h>
#include <cstdint>

// Problem constants
#define Bc 2
#define Sc 2048
#define Ec 1024
#define Hc 16
#define GK 1024
#define GN 1024

// ---------------- scratch (device globals; no allocation) ----------------
__device__ float g_X [Bc*Sc*Ec];         // x, tf32-rounded
__device__ float g_Wq[Ec*Ec];            // weights, tf32-rounded
__device__ float g_Wk[Ec*Ec];
__device__ float g_Wv[Ec*Ec];
__device__ float g_Wo[Ec*Ec];
__device__ float g_Vt[Bc*Hc*64*Sc];      // V transposed: [bh][d][s'], tf32, kv 8-group permuted
__device__ float g_Qa[Bc*Hc*Sc*128];     // augmented Q (pre-scaled by log2e), tf32, cols permuted
__device__ float g_Ka[Bc*Hc*Sc*128];
__device__ float g_AO[Bc*Sc*Ec];         // flash output, tf32-rounded

// ---------------- helpers ----------------
__device__ __forceinline__ uint32_t cvt_tf32(float f) {
    uint32_t r;
    asm("cvt.rna.tf32.f32 %0, %1;" : "=r"(r) : "f"(f));
    return r;
}
__device__ __forceinline__ float cvtf(float f) { return __uint_as_float(cvt_tf32(f)); }
__device__ __forceinline__ void mma8(float c[4], const uint32_t a[4],
                                     uint32_t b0, uint32_t b1) {
    asm volatile(
        "mma.sync.aligned.m16n8k8.row.col.f32.tf32.tf32.f32 "
        "{%0,%1,%2,%3}, {%4,%5,%6,%7}, {%8,%9}, {%0,%1,%2,%3};"
        : "+f"(c[0]), "+f"(c[1]), "+f"(c[2]), "+f"(c[3])
        : "r"(a[0]), "r"(a[1]), "r"(a[2]), "r"(a[3]), "r"(b0), "r"(b1));
}
__device__ __forceinline__ uint32_t smem_u32(const void* p) {
    uint32_t a;
    asm("{ .reg .u64 t; cvta.to.shared.u64 t, %1; cvt.u32.u64 %0, t; }" : "=r"(a) : "l"(p));
    return a;
}
__device__ __forceinline__ void cp16(uint32_t dst, const void* src) {
    asm volatile("cp.async.cg.shared.global [%0], [%1], 16;" :: "r"(dst), "l"(src));
}
#define CP_COMMIT() asm volatile("cp.async.commit_group;" ::: "memory")

// 8-group interleave: position p = 8*(c>>3) + perm8(c&7) holds semantic col c.
__device__ __host__ __forceinline__ int perm8(int r) { return ((r & 3) << 1) | (r >> 2); }

// ================= pre-round to tf32 (RNA), packed 1D grid =================
__global__ void preround5(const float4* __restrict__ x,  float4* __restrict__ dx,  int xn4,
                          const float4* __restrict__ w0, float4* __restrict__ dw0,
                          const float4* __restrict__ w1, float4* __restrict__ dw1,
                          const float4* __restrict__ w2, float4* __restrict__ dw2,
                          const float4* __restrict__ w3, float4* __restrict__ dw3, int wn4,
                          int XB, int WB)
{
    int blk = blockIdx.x;
    const float4* s;
    float4* d;
    int n4, base;
    if (blk < XB)               { s = x;  d = dx;  n4 = xn4; base = blk; }
    else if (blk < XB + WB)     { s = w0; d = dw0; n4 = wn4; base = blk - XB; }
    else if (blk < XB + 2 * WB) { s = w1; d = dw1; n4 = wn4; base = blk - XB - WB; }
    else if (blk < XB + 3 * WB) { s = w2; d = dw2; n4 = wn4; base = blk - XB - 2 * WB; }
    else                        { s = w3; d = dw3; n4 = wn4; base = blk - XB - 3 * WB; }
    int i = base * 256 + threadIdx.x;
    if (i < n4) {
        float4 v = s[i];
        v.x = cvtf(v.x); v.y = cvtf(v.y); v.z = cvtf(v.z); v.w = cvtf(v.w);
        d[i] = v;
    }
}

// ================= fused GEMM (cp.async 3-stage, 2 CTAs/SM) =================
// z==2 -> V->Vt transposed epilogue (Ct stride 133, scalar reads).
// fused&&z<2 -> helical epilogue straight to Qa/Ka (Ct stride 132, 16B-aligned rows).
// !fused -> plain C write (O projection).
#define GST 36
#define GSTG (2 * 128 * GST)
#define CTS 132     // fused-path Ct stride: 132*4B = 33*16B -> float4-aligned rows
__global__ void __launch_bounds__(256, 2)
gemm_mma3(const float* __restrict__ A,
          const float* __restrict__ W0, const float* __restrict__ W1, const float* __restrict__ W2,
          const float* __restrict__ b0, const float* __restrict__ b1, const float* __restrict__ b2,
          float* __restrict__ Cout, float* __restrict__ Vt,
          const float* __restrict__ Whel, const float* __restrict__ bhel,
          float* __restrict__ Qa, float* __restrict__ Ka, int fused)
{
    const int z = blockIdx.z;
    const float* W    = (z == 0) ? W0 : ((z == 1) ? W1 : W2);
    const float* bias = (z == 0) ? b0 : ((z == 1) ? b1 : b2);

    extern __shared__ uint32_t smg[];
    __shared__ float s_bias[128];

    const int t = threadIdx.x, wid = t >> 5, lane = t & 31;
    const int gr = lane >> 2, tg = lane & 3;
    const int row0 = blockIdx.y * 128, col0 = blockIdx.x * 128;
    const int wm = (wid & 1) * 64, wn = (wid >> 1) * 32;

    if (t < 128) s_bias[t] = bias[col0 + t];

    const uint32_t smgA = smem_u32(smg);

    auto issue = [&](int c) {
        const int st = c % 3;
        const uint32_t baseA = smgA + st * GSTG * 4;
        const uint32_t baseB = baseA + 128 * GST * 4;
        #pragma unroll
        for (int i = 0; i < 4; i++) {
            int pos = t + i * 256;
            int r = pos >> 3, q = pos & 7;
            cp16(baseA + (r * GST + q * 4) * 4, A + (size_t)(row0 + r) * GK + c * 32 + q * 4);
            cp16(baseB + (r * GST + q * 4) * 4, W + (size_t)(col0 + r) * GK + c * 32 + q * 4);
        }
        CP_COMMIT();
    };

    float acc[4][4][4] = {};
    issue(0);
    issue(1);

    const int NC = GK / 32;
    for (int c = 0; c < NC; c++) {
        if (c + 1 < NC) { asm volatile("cp.async.wait_group 1;" ::: "memory"); }
        else            { asm volatile("cp.async.wait_group 0;" ::: "memory"); }
        __syncthreads();
        if (c + 2 < NC) issue(c + 2);

        const uint32_t* Ab = smg + (c % 3) * GSTG;
        const uint32_t* Bb = Ab + 128 * GST;
        #pragma unroll
        for (int kk = 0; kk < 4; kk++) {
            const int kb = kk * 8;
            uint32_t af[4][4];
            #pragma unroll
            for (int mi = 0; mi < 4; mi++) {
                int r = wm + mi * 16 + gr;
                af[mi][0] = Ab[(r)     * GST + kb + tg];
                af[mi][1] = Ab[(r + 8) * GST + kb + tg];
                af[mi][2] = Ab[(r)     * GST + kb + tg + 4];
                af[mi][3] = Ab[(r + 8) * GST + kb + tg + 4];
            }
            #pragma unroll
            for (int nj = 0; nj < 4; nj++) {
                int n = wn + nj * 8 + gr;
                uint32_t bb0 = Bb[n * GST + kb + tg];
                uint32_t bb1 = Bb[n * GST + kb + tg + 4];
                #pragma unroll
                for (int mi = 0; mi < 4; mi++)
                    mma8(acc[mi][nj], af[mi], bb0, bb1);
            }
        }
    }

    if (z == 2) {
        // V: stage to smem (stride 133, scalar reads), write transposed+permuted g_Vt
        __syncthreads();
        float* Ct = reinterpret_cast<float*>(smg);     // 128 tokens x 133
        #pragma unroll
        for (int mi = 0; mi < 4; mi++) {
            #pragma unroll
            for (int nj = 0; nj < 4; nj++) {
                int r  = wm + mi * 16 + gr;
                int cc = wn + nj * 8 + 2 * tg;
                Ct[(r)     * 133 + cc]     = acc[mi][nj][0] + s_bias[cc];
                Ct[(r)     * 133 + cc + 1] = acc[mi][nj][1] + s_bias[cc + 1];
                Ct[(r + 8) * 133 + cc]     = acc[mi][nj][2] + s_bias[cc];
                Ct[(r + 8) * 133 + cc + 1] = acc[mi][nj][3] + s_bias[cc + 1];
            }
        }
        __syncthreads();
        const int bh_base = (row0 >> 11) * 16 + (col0 >> 6);
        const int sg0 = row0 & (Sc - 1);
        #pragma unroll
        for (int i = 0; i < 64; i++) {
            int idx = t + i * 256;
            int dl = idx >> 7, tok = idx & 127;
            float v = Ct[tok * 133 + dl];
            size_t dst = ((size_t)(bh_base + (dl >> 6)) * 64 + (dl & 63)) * Sc
                       + sg0 + (tok & ~7) + perm8(tok & 7);
            Vt[dst] = cvtf(v);
        }
    } else if (fused) {
        // ---- fused helical epilogue: this tile = 128 tokens x 2 complete heads ----
        __syncthreads();
        float* Ct = reinterpret_cast<float*>(smg);     // 128 x CTS (16B-aligned rows)
        #pragma unroll
        for (int mi = 0; mi < 4; mi++) {
            #pragma unroll
            for (int nj = 0; nj < 4; nj++) {
                int r  = wm + mi * 16 + gr;
                int cc = wn + nj * 8 + 2 * tg;
                Ct[(r)     * CTS + cc]     = acc[mi][nj][0] + s_bias[cc];
                Ct[(r)     * CTS + cc + 1] = acc[mi][nj][1] + s_bias[cc + 1];
                Ct[(r + 8) * CTS + cc]     = acc[mi][nj][2] + s_bias[cc];
                Ct[(r + 8) * CTS + cc + 1] = acc[mi][nj][3] + s_bias[cc + 1];
            }
        }
        float* Wtmp = Ct + 128 * CTS;       // 64 x 68
        float* WsT  = Wtmp + 64 * 68;       // 64 x 64
        float* bs   = WsT + 64 * 64;        // 64

        const float LOG2E = 1.4426950408889634f;
        float* Aug = (z == 0) ? Qa : Ka;
        const float dsc = (z == 0) ? (0.5f / 8.0f  * LOG2E) : 1.0f;
        const float hsc = (z == 0) ? (0.5f / 32.0f * LOG2E) : 1.0f;
        const int bb    = row0 >> 11;
        const int sbase = row0 & (Sc - 1);
        const int h0    = col0 >> 6;

        const int lr = lane >> 3, g = lane & 7;
        const int rbase = wid * 16 + lr * 4;

        __syncthreads();                    // Ct visible

        for (int hh = 0; hh < 2; hh++) {
            const int h = h0 + hh;
            const size_t bhRow = (size_t)(bb * Hc + h) * Sc;

            // stage Whel head h (e-major, coalesced) + bhel
            #pragma unroll
            for (int i = 0; i < 4; i++) {
                int pos = t + i * 256;
                int e = pos >> 4, d4 = pos & 15;
                float4 v = *reinterpret_cast<const float4*>(Whel + ((size_t)h * 64 + e) * 64 + d4 * 4);
                *reinterpret_cast<float4*>(Wtmp + e * 68 + d4 * 4) = v;
            }
            if (t < 64) bs[t] = bhel[h * 64 + t];

            // dot part of Aug for this head (float4 reads now 16B-aligned)
            {
                int r = t & 127, c8b = (t >> 7) * 4;
                const float* crow = Ct + r * CTS + hh * 64;
                float* drow = Aug + (bhRow + sbase + r) * 128;
                #pragma unroll
                for (int j = 0; j < 4; j++) {
                    int c8 = c8b + j;
                    float4 a = *reinterpret_cast<const float4*>(crow + c8 * 8);
                    float4 c = *reinterpret_cast<const float4*>(crow + c8 * 8 + 4);
                    float* dst = drow + c8 * 8;
                    *reinterpret_cast<float2*>(dst)     = { cvtf(a.x * dsc), cvtf(c.x * dsc) };
                    *reinterpret_cast<float2*>(dst + 2) = { cvtf(a.y * dsc), cvtf(c.y * dsc) };
                    *reinterpret_cast<float2*>(dst + 4) = { cvtf(a.z * dsc), cvtf(c.z * dsc) };
                    *reinterpret_cast<float2*>(dst + 6) = { cvtf(a.w * dsc), cvtf(c.w * dsc) };
                }
            }
            __syncthreads();

            // transpose Wtmp -> WsT (d-major)
            #pragma unroll
            for (int i = 0; i < 16; i++) {
                int pos = t + i * 256;
                int d = pos >> 6, e = pos & 63;
                WsT[d * 64 + e] = Wtmp[e * 68 + d];
            }
            __syncthreads();

            // helical projection: 4 tokens x 8 cols per thread (identical math to hel_fuse2)
            float a2[4][8] = {};
            #pragma unroll 4
            for (int d = 0; d < 64; d++) {
                float a[4];
                #pragma unroll
                for (int i = 0; i < 4; i++) a[i] = Ct[(rbase + i) * CTS + hh * 64 + d];
                float4 w0 = *reinterpret_cast<const float4*>(WsT + d * 64 + g * 8);
                float4 w1 = *reinterpret_cast<const float4*>(WsT + d * 64 + g * 8 + 4);
                #pragma unroll
                for (int i = 0; i < 4; i++) {
                    a2[i][0] += a[i] * w0.x;  a2[i][1] += a[i] * w0.y;
                    a2[i][2] += a[i] * w0.z;  a2[i][3] += a[i] * w0.w;
                    a2[i][4] += a[i] * w1.x;  a2[i][5] += a[i] * w1.y;
                    a2[i][6] += a[i] * w1.z;  a2[i][7] += a[i] * w1.w;
                }
            }

            // bias + pair-normalize + inverse-scramble scatter
            #pragma unroll
            for (int i = 0; i < 4; i++) {
                int s_src = sbase + rbase + i;
                size_t orow1 = (bhRow + (s_src >> 1)) * 128;
                size_t orow2 = orow1 + (size_t)(Sc / 2) * 128;
                int par = s_src & 1;
                #pragma unroll
                for (int jj = 0; jj < 4; jj++) {
                    float x = a2[i][2 * jj]     + bs[g * 8 + 2 * jj];
                    float y = a2[i][2 * jj + 1] + bs[g * 8 + 2 * jj + 1];
                    float nrm = sqrtf(x * x + y * y);
                    float inv = hsc / fmaxf(nrm, 1e-12f);
                    int col = 64 + g * 8 + perm8(2 * jj + par);
                    Aug[orow1 + col] = cvtf(x * inv);
                    Aug[orow2 + col] = cvtf(y * inv);
                }
            }
            __syncthreads();    // protect Wtmp/WsT/bs before next head
        }
    } else {
        // plain C + bias (O projection)
        #pragma unroll
        for (int mi = 0; mi < 4; mi++) {
            #pragma unroll
            for (int nj = 0; nj < 4; nj++) {
                int r  = row0 + wm + mi * 16 + gr;
                int cc = col0 + wn + nj * 8 + 2 * tg;
                int bi = wn + nj * 8 + 2 * tg;
                float2 lo = { acc[mi][nj][0] + s_bias[bi], acc[mi][nj][1] + s_bias[bi + 1] };
                float2 hi = { acc[mi][nj][2] + s_bias[bi], acc[mi][nj][3] + s_bias[bi + 1] };
                *reinterpret_cast<float2*>(Cout + (size_t)r * GN + cc)       = lo;
                *reinterpret_cast<float2*>(Cout + (size_t)(r + 8) * GN + cc) = hi;
            }
        }
    }
}

// ================= flash attention: QT=128/KT=32, 4-stage, exp2, 2 CTAs/SM (unchanged) =================
#define QT 128
#define KT 32
#define KSS 136
#define VSS 40
#define FSTG (KT * KSS + 64 * VSS)

__global__ void __launch_bounds__(256, 2)
flash_mma(const float* __restrict__ Qa, const float* __restrict__ Ka,
          const float* __restrict__ Vt, float* __restrict__ O)
{
    extern __shared__ uint32_t smf[];

    const int bh = blockIdx.y;
    const int b  = bh >> 4, h = bh & 15;
    const int s0 = blockIdx.x * QT;
    const int t  = threadIdx.x, wid = t >> 5, lane = t & 31;
    const int gr = lane >> 2, tg = lane & 3;
    const int prow = wid * 16 + gr;

    const uint32_t smfA = smem_u32(smf);

    const int srcA = (lane & 28) | (tg >> 1);
    const int srcB = srcA + 2;
    const bool oddsel = (tg & 1);

    uint32_t qf[16][4];
    {
        const float* Qb = Qa + ((size_t)bh * Sc + s0) * 128;
        #pragma unroll
        for (int kk = 0; kk < 16; kk++) {
            float2 lo = *reinterpret_cast<const float2*>(Qb + (size_t)(prow)     * 128 + kk * 8 + 2 * tg);
            float2 hi = *reinterpret_cast<const float2*>(Qb + (size_t)(prow + 8) * 128 + kk * 8 + 2 * tg);
            qf[kk][0] = __float_as_uint(lo.x);
            qf[kk][1] = __float_as_uint(hi.x);
            qf[kk][2] = __float_as_uint(lo.y);
            qf[kk][3] = __float_as_uint(hi.y);
        }
    }

    auto issue = [&](int it) {
        const int t0 = it * KT;
        const uint32_t baseK = smfA + (it & 3) * FSTG * 4;
        const uint32_t baseV = baseK + KT * KSS * 4;
        const float* Kb = Ka + ((size_t)bh * Sc + t0) * 128;
        #pragma unroll
        for (int i = 0; i < 4; i++) {
            int pos = t + i * 256;
            int r = pos >> 5, c = pos & 31;
            cp16(baseK + (r * KSS + c * 4) * 4, Kb + (size_t)r * 128 + c * 4);
        }
        const float* Vb = Vt + (size_t)bh * 64 * Sc + t0;
        #pragma unroll
        for (int i = 0; i < 2; i++) {
            int pos = t + i * 256;
            int r = pos >> 3, c = pos & 7;
            cp16(baseV + (r * VSS + c * 4) * 4, Vb + (size_t)r * Sc + c * 4);
        }
        CP_COMMIT();
    };

    issue(0);
    issue(1);
    issue(2);

    float l0 = 0.0f, l1 = 0.0f;
    float o[8][4] = {};

    const int NIT = Sc / KT;
    for (int it = 0; it < NIT; it++) {
        const int rem = NIT - 1 - it;
        if (rem >= 2)      { asm volatile("cp.async.wait_group 2;" ::: "memory"); }
        else if (rem == 1) { asm volatile("cp.async.wait_group 1;" ::: "memory"); }
        else               { asm volatile("cp.async.wait_group 0;" ::: "memory"); }
        __syncthreads();
        if (it + 3 < NIT) issue(it + 3);

        const uint32_t* Kp = smf + (it & 3) * FSTG;
        const uint32_t* Vp = Kp + KT * KSS;

        float s[4][4] = {};
        #pragma unroll
        for (int kk = 0; kk < 16; kk++) {
            const int kb = kk * 8;
            #pragma unroll
            for (int nj = 0; nj < 4; nj++) {
                uint2 bb = *reinterpret_cast<const uint2*>(Kp + (nj * 8 + gr) * KSS + kb + 2 * tg);
                mma8(s[nj], qf[kk], bb.x, bb.y);
            }
        }

        #pragma unroll
        for (int nj = 0; nj < 4; nj++) {
            s[nj][0] = exp2f(s[nj][0]);
            s[nj][1] = exp2f(s[nj][1]);
            s[nj][2] = exp2f(s[nj][2]);
            s[nj][3] = exp2f(s[nj][3]);
            l0 += s[nj][0] + s[nj][1];
            l1 += s[nj][2] + s[nj][3];
        }

        #pragma unroll
        for (int kk = 0; kk < 4; kk++) {
            float t00 = __shfl_sync(0xffffffffu, s[kk][0], srcA);
            float t01 = __shfl_sync(0xffffffffu, s[kk][1], srcA);
            float t10 = __shfl_sync(0xffffffffu, s[kk][2], srcA);
            float t11 = __shfl_sync(0xffffffffu, s[kk][3], srcA);
            float t20 = __shfl_sync(0xffffffffu, s[kk][0], srcB);
            float t21 = __shfl_sync(0xffffffffu, s[kk][1], srcB);
            float t30 = __shfl_sync(0xffffffffu, s[kk][2], srcB);
            float t31 = __shfl_sync(0xffffffffu, s[kk][3], srcB);
            uint32_t af[4];
            af[0] = cvt_tf32(oddsel ? t01 : t00);
            af[1] = cvt_tf32(oddsel ? t11 : t10);
            af[2] = cvt_tf32(oddsel ? t21 : t20);
            af[3] = cvt_tf32(oddsel ? t31 : t30);
            const int kb = kk * 8;
            #pragma unroll
            for (int nj = 0; nj < 8; nj++) {
                uint2 bb = *reinterpret_cast<const uint2*>(Vp + (nj * 8 + gr) * VSS + kb + 2 * tg);
                mma8(o[nj], af, bb.x, bb.y);
            }
        }
    }

    l0 += __shfl_xor_sync(0xffffffffu, l0, 1);
    l0 += __shfl_xor_sync(0xffffffffu, l0, 2);
    l1 += __shfl_xor_sync(0xffffffffu, l1, 1);
    l1 += __shfl_xor_sync(0xffffffffu, l1, 2);

    const float invA = 1.0f / l0, invB = 1.0f / l1;
    const int rowA = s0 + prow;
    #pragma unroll
    for (int nj = 0; nj < 8; nj++) {
        int col = h * 64 + nj * 8 + 2 * tg;
        float2 lo = { cvtf(o[nj][0] * invA), cvtf(o[nj][1] * invA) };
        float2 hi = { cvtf(o[nj][2] * invB), cvtf(o[nj][3] * invB) };
        *reinterpret_cast<float2*>(O + (size_t)(b * Sc + rowA) * Ec + col)     = lo;
        *reinterpret_cast<float2*>(O + (size_t)(b * Sc + rowA + 8) * Ec + col) = hi;
    }
}

// ---------------- host launcher ----------------
extern "C" void kernel_launch(void* const* d_in, const int* in_sizes, int n_in,
                              void* d_out, int out_size)
{
    const float* x    = (const float*)d_in[0];
    const float* Wq   = (const float*)d_in[1];
    const float* bq   = (const float*)d_in[2];
    const float* Wk   = (const float*)d_in[3];
    const float* bk   = (const float*)d_in[4];
    const float* Wv   = (const float*)d_in[5];
    const float* bv   = (const float*)d_in[6];
    const float* Wo   = (const float*)d_in[7];
    const float* bo   = (const float*)d_in[8];
    const float* Whel = (const float*)d_in[9];
    const float* bhel = (const float*)d_in[10];
    float* out = (float*)d_out;

    void *pX, *pWq, *pWk, *pWv, *pWo, *pVt, *pQa, *pKa, *pAO;
    cudaGetSymbolAddress(&pX,  g_X);
    cudaGetSymbolAddress(&pWq, g_Wq);
    cudaGetSymbolAddress(&pWk, g_Wk);
    cudaGetSymbolAddress(&pWv, g_Wv);
    cudaGetSymbolAddress(&pWo, g_Wo);
    cudaGetSymbolAddress(&pVt, g_Vt);
    cudaGetSymbolAddress(&pQa, g_Qa);
    cudaGetSymbolAddress(&pKa, g_Ka);
    cudaGetSymbolAddress(&pAO, g_AO);

    const int GEMM_SMEM  = 3 * GSTG * 4;        // 110592 (fused overlay needs 101,632)
    const int FLASH_SMEM = 4 * FSTG * 4;        // 110592
    cudaFuncSetAttribute(gemm_mma3, cudaFuncAttributeMaxDynamicSharedMemorySize, GEMM_SMEM);
    cudaFuncSetAttribute(flash_mma, cudaFuncAttributeMaxDynamicSharedMemorySize, FLASH_SMEM);

    dim3 blk(256);

    // 0) pre-round x and the 4 weights, packed 1D grid
    const int xN4 = Bc * Sc * Ec / 4;
    const int wN4 = Ec * Ec / 4;
    const int XB = (xN4 + 255) / 256;
    const int WB = (wN4 + 255) / 256;
    preround5<<<XB + 4 * WB, blk>>>((const float4*)x,  (float4*)pX,  xN4,
                                    (const float4*)Wq, (float4*)pWq,
                                    (const float4*)Wk, (float4*)pWk,
                                    (const float4*)Wv, (float4*)pWv,
                                    (const float4*)Wo, (float4*)pWo, wN4,
                                    XB, WB);

    // 1) Q, K, V projections with fused helical epilogue (Q->Qa, K->Ka, V->Vt)
    dim3 qkvGrid(GN / 128, (Bc * Sc) / 128, 3);
    gemm_mma3<<<qkvGrid, blk, GEMM_SMEM>>>((const float*)pX,
                                           (const float*)pWq, (const float*)pWk, (const float*)pWv,
                                           bq, bk, bv,
                                           nullptr, (float*)pVt,
                                           Whel, bhel, (float*)pQa, (float*)pKa, 1);

    // 2) flash attention
    dim3 faGrid(Sc / QT, Bc * Hc);
    flash_mma<<<faGrid, blk, FLASH_SMEM>>>((const float*)pQa, (const float*)pKa,
                                           (const float*)pVt, (float*)pAO);

    // 3) output projection (plain epilogue)
    dim3 oGrid(GN / 128, (Bc * Sc) / 128, 1);
    gemm_mma3<<<oGrid, blk, GEMM_SMEM>>>((const float*)pAO,
                                         (const float*)pWo, (const float*)pWo, (const float*)pWo,
                                         bo, bo, bo,
                                         out, nullptr,
                                         Whel, bhel, nullptr, nullptr, 0);
}